// round 1
// baseline (speedup 1.0000x reference)
#include <cuda_runtime.h>
#include <cstdint>

#define NN 50000
#define EE 800000
#define IN_DIM 128
#define EDGE_DIM 32
#define OUT_DIM 128

// Scratch (device globals; no dynamic allocation allowed)
__device__ float g_h1[(size_t)NN * OUT_DIM];     // W1 @ nfeat[n] + b_ne
__device__ int   g_neigh[(size_t)NN * OUT_DIM];  // float bits, segment max accumulator
__device__ float g_WcT[EDGE_DIM * OUT_DIM];      // (W2 @ W_edge) transposed: [c][o]
__device__ float g_W1T[IN_DIM * OUT_DIM];        // W1 transposed: [k][j]
__device__ float g_WsT[IN_DIM * OUT_DIM];        // W_self transposed: [k][j]

// ---------------- prep: Wc = W2 @ W_edge, stored transposed ----------------
__global__ void k_wc(const float* __restrict__ W_ne, const float* __restrict__ W_edge) {
    int c = blockIdx.x;    // 0..31
    int o = threadIdx.x;   // 0..127
    float s = 0.f;
    #pragma unroll 8
    for (int j = 0; j < 128; j++)
        s += W_ne[o * 256 + 128 + j] * W_edge[j * 32 + c];
    g_WcT[c * 128 + o] = s;
}

// ---------------- prep: transpose W1 and W_self ----------------
__global__ void k_transpose(const float* __restrict__ W_ne, const float* __restrict__ W_self) {
    int idx = blockIdx.x * blockDim.x + threadIdx.x;  // 16384
    int j = idx >> 7, k = idx & 127;
    g_W1T[k * 128 + j] = W_ne[j * 256 + k];
    g_WsT[k * 128 + j] = W_self[j * 128 + k];
}

// ---------------- zero the neigh accumulator ----------------
__global__ void k_zero() {
    int idx = blockIdx.x * blockDim.x + threadIdx.x;  // over NN*128/4
    int4 z = {0, 0, 0, 0};
    ((int4*)g_neigh)[idx] = z;
}

// ---------------- node GEMM: h1 = nfeat@W1.T + b_ne ; out(self) = nfeat@W_self.T + b_self
// one warp per node; lane owns 4 consecutive output dims (float4)
__global__ void k_node(const float* __restrict__ nfeat,
                       const float* __restrict__ b_ne,
                       const float* __restrict__ b_self,
                       float* __restrict__ out_self) {
    int warp = (blockIdx.x * blockDim.x + threadIdx.x) >> 5;
    int lane = threadIdx.x & 31;
    if (warp >= NN) return;
    const float* x = nfeat + (size_t)warp * 128;

    float xv[4];
    #pragma unroll
    for (int ch = 0; ch < 4; ch++) xv[ch] = x[ch * 32 + lane];

    int j4 = lane * 4;
    float4 ah = {0.f, 0.f, 0.f, 0.f};
    float4 as = {0.f, 0.f, 0.f, 0.f};

    #pragma unroll
    for (int ch = 0; ch < 4; ch++) {
        #pragma unroll
        for (int c = 0; c < 32; c++) {
            float xk = __shfl_sync(0xffffffffu, xv[ch], c);
            int k = ch * 32 + c;
            float4 w1 = *(const float4*)&g_W1T[k * 128 + j4];
            float4 ws = *(const float4*)&g_WsT[k * 128 + j4];
            ah.x = fmaf(w1.x, xk, ah.x); ah.y = fmaf(w1.y, xk, ah.y);
            ah.z = fmaf(w1.z, xk, ah.z); ah.w = fmaf(w1.w, xk, ah.w);
            as.x = fmaf(ws.x, xk, as.x); as.y = fmaf(ws.y, xk, as.y);
            as.z = fmaf(ws.z, xk, as.z); as.w = fmaf(ws.w, xk, as.w);
        }
    }
    float4 bh = *(const float4*)&b_ne[j4];
    float4 bs = *(const float4*)&b_self[j4];
    ah.x += bh.x; ah.y += bh.y; ah.z += bh.z; ah.w += bh.w;
    as.x += bs.x; as.y += bs.y; as.z += bs.z; as.w += bs.w;
    *(float4*)&g_h1[(size_t)warp * 128 + j4] = ah;
    *(float4*)&out_self[(size_t)warp * 128 + j4] = as;
}

// ---------------- edge kernel: m = relu(h1[src] + Wc@etype[e]) ; atomicMax into neigh[dst]
__global__ void k_edge(const float* __restrict__ etype,
                       const int* __restrict__ src,
                       const int* __restrict__ dst) {
    __shared__ float sW[EDGE_DIM * 128];
    for (int i = threadIdx.x; i < EDGE_DIM * 128; i += blockDim.x)
        sW[i] = g_WcT[i];
    __syncthreads();

    int lane = threadIdx.x & 31;
    int warpInBlock = threadIdx.x >> 5;
    int warpsPerBlock = blockDim.x >> 5;
    int gw = blockIdx.x * warpsPerBlock + warpInBlock;
    int totalWarps = gridDim.x * warpsPerBlock;
    int j4 = lane * 4;

    for (int e = gw; e < EE; e += totalWarps) {
        int s = src[e];
        int d = dst[e];
        float ev = etype[(size_t)e * 32 + lane];
        float4 acc = *(const float4*)&g_h1[(size_t)s * 128 + j4];
        #pragma unroll
        for (int c = 0; c < 32; c++) {
            float xc = __shfl_sync(0xffffffffu, ev, c);
            float4 w = *(const float4*)&sW[c * 128 + j4];
            acc.x = fmaf(w.x, xc, acc.x);
            acc.y = fmaf(w.y, xc, acc.y);
            acc.z = fmaf(w.z, xc, acc.z);
            acc.w = fmaf(w.w, xc, acc.w);
        }
        acc.x = fmaxf(acc.x, 0.f); acc.y = fmaxf(acc.y, 0.f);
        acc.z = fmaxf(acc.z, 0.f); acc.w = fmaxf(acc.w, 0.f);
        int* np = &g_neigh[(size_t)d * 128 + j4];
        // relu outputs are >= 0, so float ordering == signed-int-bit ordering; init 0 is identity
        atomicMax(np + 0, __float_as_int(acc.x));
        atomicMax(np + 1, __float_as_int(acc.y));
        atomicMax(np + 2, __float_as_int(acc.z));
        atomicMax(np + 3, __float_as_int(acc.w));
    }
}

// ---------------- final: out = (1+eps)*neigh + out(self) ----------------
__global__ void k_final(const float* __restrict__ eps, float* __restrict__ out) {
    float s = 1.0f + eps[0];
    int idx = blockIdx.x * blockDim.x + threadIdx.x;  // over NN*128/4
    float4 o = ((float4*)out)[idx];
    int4 nb = ((const int4*)g_neigh)[idx];
    o.x = fmaf(s, __int_as_float(nb.x), o.x);
    o.y = fmaf(s, __int_as_float(nb.y), o.y);
    o.z = fmaf(s, __int_as_float(nb.z), o.z);
    o.w = fmaf(s, __int_as_float(nb.w), o.w);
    ((float4*)out)[idx] = o;
}

extern "C" void kernel_launch(void* const* d_in, const int* in_sizes, int n_in,
                              void* d_out, int out_size) {
    const float* nfeat  = (const float*)d_in[0];
    const float* etype  = (const float*)d_in[1];
    const int*   src    = (const int*)d_in[2];
    const int*   dst    = (const int*)d_in[3];
    const float* W_edge = (const float*)d_in[4];
    const float* W_ne   = (const float*)d_in[5];
    const float* b_ne   = (const float*)d_in[6];
    const float* W_self = (const float*)d_in[7];
    const float* b_self = (const float*)d_in[8];
    const float* eps    = (const float*)d_in[9];
    float* out = (float*)d_out;

    k_wc<<<32, 128>>>(W_ne, W_edge);
    k_transpose<<<64, 256>>>(W_ne, W_self);
    k_zero<<<(NN * OUT_DIM / 4) / 256, 256>>>();
    k_node<<<NN / 8, 256>>>(nfeat, b_ne, b_self, out);
    k_edge<<<2048, 256>>>(etype, src, dst);
    k_final<<<(NN * OUT_DIM / 4) / 256, 256>>>(eps, out);
}

// round 2
// speedup vs baseline: 1.7216x; 1.7216x over previous
#include <cuda_runtime.h>
#include <cstdint>

#define NN 50000
#define EE 800000
#define IN_DIM 128
#define EDGE_DIM 32
#define OUT_DIM 128

// Scratch (device globals; no dynamic allocation allowed)
__device__ float g_h1[(size_t)NN * OUT_DIM];     // W1 @ nfeat[n] + b_ne
__device__ float g_neigh[(size_t)NN * OUT_DIM];  // segment max result
__device__ float g_WcT[EDGE_DIM * OUT_DIM];      // (W2 @ W_edge) transposed: [c][o]
__device__ float g_W1T[IN_DIM * OUT_DIM];        // W1 transposed: [k][j]
__device__ float g_WsT[IN_DIM * OUT_DIM];        // W_self transposed: [k][j]
__device__ int   g_deg[NN];                      // degree per dst
__device__ int   g_off[NN];                      // exclusive prefix (CSR row ptr)
__device__ int   g_cursor[NN];                   // scatter cursors (mutated copy of off)
__device__ int   g_eperm[EE];                    // edge ids grouped by dst

// ---------------- prep: Wc = W2 @ W_edge, stored transposed ----------------
__global__ void k_wc(const float* __restrict__ W_ne, const float* __restrict__ W_edge) {
    int c = blockIdx.x;    // 0..31
    int o = threadIdx.x;   // 0..127
    float s = 0.f;
    #pragma unroll 8
    for (int j = 0; j < 128; j++)
        s += W_ne[o * 256 + 128 + j] * W_edge[j * 32 + c];
    g_WcT[c * 128 + o] = s;
}

// ---------------- prep: transpose W1 and W_self; zero deg ----------------
__global__ void k_prep(const float* __restrict__ W_ne, const float* __restrict__ W_self) {
    int idx = blockIdx.x * blockDim.x + threadIdx.x;  // 16384
    int j = idx >> 7, k = idx & 127;
    g_W1T[k * 128 + j] = W_ne[j * 256 + k];
    g_WsT[k * 128 + j] = W_self[j * 128 + k];
    // zero degree counters alongside (16384 threads cover 50000 in stride)
    for (int n = idx; n < NN; n += 16384) g_deg[n] = 0;
}

// ---------------- degree count ----------------
__global__ void k_count(const int* __restrict__ dst) {
    int e = blockIdx.x * blockDim.x + threadIdx.x;
    if (e < EE) atomicAdd(&g_deg[dst[e]], 1);
}

// ---------------- exclusive scan of g_deg (single block, 1024 threads) ----------------
__global__ void k_scan() {
    __shared__ int s[1024];
    int t = threadIdx.x;
    const int PER = 49;  // ceil(50000/1024)
    int base = t * PER;
    int sum = 0;
    for (int i = 0; i < PER; i++) {
        int n = base + i;
        if (n < NN) sum += g_deg[n];
    }
    s[t] = sum;
    __syncthreads();
    // Hillis-Steele inclusive scan
    for (int d = 1; d < 1024; d <<= 1) {
        int v = (t >= d) ? s[t - d] : 0;
        __syncthreads();
        s[t] += v;
        __syncthreads();
    }
    int run = s[t] - sum;  // exclusive offset for this thread's chunk
    for (int i = 0; i < PER; i++) {
        int n = base + i;
        if (n < NN) {
            g_off[n] = run;
            g_cursor[n] = run;
            run += g_deg[n];
        }
    }
}

// ---------------- scatter edge ids into dst-grouped order ----------------
__global__ void k_scatter(const int* __restrict__ dst) {
    int e = blockIdx.x * blockDim.x + threadIdx.x;
    if (e < EE) {
        int d = dst[e];
        int p = atomicAdd(&g_cursor[d], 1);
        g_eperm[p] = e;
    }
}

// ---------------- node GEMM: 4 nodes per warp, weight loads amortized x4 ----------------
__global__ void k_node(const float* __restrict__ nfeat,
                       const float* __restrict__ b_ne,
                       const float* __restrict__ b_self,
                       float* __restrict__ out_self) {
    int warp = (blockIdx.x * blockDim.x + threadIdx.x) >> 5;
    int lane = threadIdx.x & 31;
    int n0 = warp * 4;
    if (n0 >= NN) return;

    float xv[4][4];
    #pragma unroll
    for (int nk = 0; nk < 4; nk++)
        #pragma unroll
        for (int ch = 0; ch < 4; ch++)
            xv[nk][ch] = nfeat[(size_t)(n0 + nk) * 128 + ch * 32 + lane];

    int j4 = lane * 4;
    float4 ah[4], as[4];
    #pragma unroll
    for (int nk = 0; nk < 4; nk++) { ah[nk] = make_float4(0,0,0,0); as[nk] = make_float4(0,0,0,0); }

    #pragma unroll
    for (int ch = 0; ch < 4; ch++) {
        #pragma unroll
        for (int c = 0; c < 32; c++) {
            int k = ch * 32 + c;
            float4 w1 = *(const float4*)&g_W1T[k * 128 + j4];
            float4 ws = *(const float4*)&g_WsT[k * 128 + j4];
            #pragma unroll
            for (int nk = 0; nk < 4; nk++) {
                float xk = __shfl_sync(0xffffffffu, xv[nk][ch], c);
                ah[nk].x = fmaf(w1.x, xk, ah[nk].x); ah[nk].y = fmaf(w1.y, xk, ah[nk].y);
                ah[nk].z = fmaf(w1.z, xk, ah[nk].z); ah[nk].w = fmaf(w1.w, xk, ah[nk].w);
                as[nk].x = fmaf(ws.x, xk, as[nk].x); as[nk].y = fmaf(ws.y, xk, as[nk].y);
                as[nk].z = fmaf(ws.z, xk, as[nk].z); as[nk].w = fmaf(ws.w, xk, as[nk].w);
            }
        }
    }
    float4 bh = *(const float4*)&b_ne[j4];
    float4 bs = *(const float4*)&b_self[j4];
    #pragma unroll
    for (int nk = 0; nk < 4; nk++) {
        float4 a = ah[nk], b = as[nk];
        a.x += bh.x; a.y += bh.y; a.z += bh.z; a.w += bh.w;
        b.x += bs.x; b.y += bs.y; b.z += bs.z; b.w += bs.w;
        *(float4*)&g_h1[(size_t)(n0 + nk) * 128 + j4] = a;
        *(float4*)&out_self[(size_t)(n0 + nk) * 128 + j4] = b;
    }
}

// ---------------- edge kernel: warp per dst node, 4 edges per pass, no atomics ----------------
__global__ void k_edge(const float* __restrict__ etype,
                       const int* __restrict__ src) {
    __shared__ float sW[EDGE_DIM * 128];
    for (int i = threadIdx.x; i < EDGE_DIM * 128; i += blockDim.x)
        sW[i] = g_WcT[i];
    __syncthreads();

    int lane = threadIdx.x & 31;
    int warp = (blockIdx.x * blockDim.x + threadIdx.x) >> 5;
    if (warp >= NN) return;
    int d = warp;
    int start = g_off[d];
    int cnt = g_deg[d];
    int j4 = lane * 4;

    float4 best = make_float4(0.f, 0.f, 0.f, 0.f);

    for (int i = 0; i < cnt; i += 4) {
        int m = cnt - i; if (m > 4) m = 4;
        float ev[4];
        float4 acc[4];
        int e0 = g_eperm[start + i];
        #pragma unroll
        for (int k = 0; k < 4; k++) {
            int e = (k < m) ? g_eperm[start + i + k] : e0;
            int s = src[e];
            ev[k] = etype[(size_t)e * 32 + lane];
            acc[k] = *(const float4*)&g_h1[(size_t)s * 128 + j4];
        }
        #pragma unroll
        for (int c = 0; c < 32; c++) {
            float4 w = *(const float4*)&sW[c * 128 + j4];
            #pragma unroll
            for (int k = 0; k < 4; k++) {
                float xc = __shfl_sync(0xffffffffu, ev[k], c);
                acc[k].x = fmaf(w.x, xc, acc[k].x);
                acc[k].y = fmaf(w.y, xc, acc[k].y);
                acc[k].z = fmaf(w.z, xc, acc[k].z);
                acc[k].w = fmaf(w.w, xc, acc[k].w);
            }
        }
        // best starts at 0 >= 0, so relu is absorbed by the max
        #pragma unroll
        for (int k = 0; k < 4; k++) {
            if (k < m) {
                best.x = fmaxf(best.x, acc[k].x);
                best.y = fmaxf(best.y, acc[k].y);
                best.z = fmaxf(best.z, acc[k].z);
                best.w = fmaxf(best.w, acc[k].w);
            }
        }
    }
    *(float4*)&g_neigh[(size_t)d * 128 + j4] = best;
}

// ---------------- final: out = (1+eps)*neigh + out(self) ----------------
__global__ void k_final(const float* __restrict__ eps, float* __restrict__ out) {
    float s = 1.0f + eps[0];
    int idx = blockIdx.x * blockDim.x + threadIdx.x;  // over NN*128/4
    float4 o = ((float4*)out)[idx];
    float4 nb = ((const float4*)g_neigh)[idx];
    o.x = fmaf(s, nb.x, o.x);
    o.y = fmaf(s, nb.y, o.y);
    o.z = fmaf(s, nb.z, o.z);
    o.w = fmaf(s, nb.w, o.w);
    ((float4*)out)[idx] = o;
}

extern "C" void kernel_launch(void* const* d_in, const int* in_sizes, int n_in,
                              void* d_out, int out_size) {
    const float* nfeat  = (const float*)d_in[0];
    const float* etype  = (const float*)d_in[1];
    const int*   src    = (const int*)d_in[2];
    const int*   dst    = (const int*)d_in[3];
    const float* W_edge = (const float*)d_in[4];
    const float* W_ne   = (const float*)d_in[5];
    const float* b_ne   = (const float*)d_in[6];
    const float* W_self = (const float*)d_in[7];
    const float* b_self = (const float*)d_in[8];
    const float* eps    = (const float*)d_in[9];
    float* out = (float*)d_out;

    k_wc<<<32, 128>>>(W_ne, W_edge);
    k_prep<<<64, 256>>>(W_ne, W_self);
    k_count<<<(EE + 255) / 256, 256>>>(dst);
    k_scan<<<1, 1024>>>();
    k_scatter<<<(EE + 255) / 256, 256>>>(dst);
    k_node<<<(NN / 4 + 7) / 8, 256>>>(nfeat, b_ne, b_self, out);
    k_edge<<<(NN + 7) / 8, 256>>>(etype, src);
    k_final<<<(NN * OUT_DIM / 4) / 256, 256>>>(eps, out);
}

// round 3
// speedup vs baseline: 1.9399x; 1.1268x over previous
#include <cuda_runtime.h>
#include <cstdint>

#define NN 50000
#define EE 800000
#define IN_DIM 128
#define EDGE_DIM 32
#define OUT_DIM 128

// Scratch (device globals; no dynamic allocation allowed)
__device__ float g_h1[(size_t)NN * OUT_DIM];     // W1 @ nfeat[n] + b_ne
__device__ float g_WcT[EDGE_DIM * OUT_DIM];      // (W2 @ W_edge) transposed: [c][o]
__device__ float g_W1T[IN_DIM * OUT_DIM];        // W1 transposed: [k][j]
__device__ float g_WsT[IN_DIM * OUT_DIM];        // W_self transposed: [k][j]
__device__ int   g_deg[NN];                      // degree per dst
__device__ int   g_incl[NN];                     // per-block inclusive scan
__device__ int   g_off[NN];                      // exclusive prefix (CSR row ptr)
__device__ int   g_cursor[NN];                   // scatter cursors
__device__ int   g_bsum[64];                     // block sums for scan
__device__ int   g_bpre[64];                     // exclusive scan of block sums
__device__ int   g_eperm[EE];                    // edge ids grouped by dst

#define SCAN_BLOCKS 49   // ceil(50000/1024)

// ---------------- prep: Wc = W2 @ W_edge, stored transposed ----------------
__global__ void k_wc(const float* __restrict__ W_ne, const float* __restrict__ W_edge) {
    int c = blockIdx.x;    // 0..31
    int o = threadIdx.x;   // 0..127
    float s = 0.f;
    #pragma unroll 8
    for (int j = 0; j < 128; j++)
        s += W_ne[o * 256 + 128 + j] * W_edge[j * 32 + c];
    g_WcT[c * 128 + o] = s;
}

// ---------------- prep: transpose W1 and W_self; zero deg ----------------
__global__ void k_prep(const float* __restrict__ W_ne, const float* __restrict__ W_self) {
    int idx = blockIdx.x * blockDim.x + threadIdx.x;  // 16384
    int j = idx >> 7, k = idx & 127;
    g_W1T[k * 128 + j] = W_ne[j * 256 + k];
    g_WsT[k * 128 + j] = W_self[j * 128 + k];
    for (int n = idx; n < NN; n += 16384) g_deg[n] = 0;
}

// ---------------- degree count ----------------
__global__ void k_count(const int* __restrict__ dst) {
    int e = blockIdx.x * blockDim.x + threadIdx.x;
    if (e < EE) atomicAdd(&g_deg[dst[e]], 1);
}

// ---------------- scan phase A: per-block inclusive scan (coalesced) ----------------
__global__ void k_scanA() {
    int n = blockIdx.x * 1024 + threadIdx.x;
    int lane = threadIdx.x & 31, w = threadIdx.x >> 5;
    int v = (n < NN) ? g_deg[n] : 0;
    int x = v;
    #pragma unroll
    for (int d = 1; d < 32; d <<= 1) {
        int y = __shfl_up_sync(0xffffffffu, x, d);
        if (lane >= d) x += y;
    }
    __shared__ int ws[32];
    if (lane == 31) ws[w] = x;
    __syncthreads();
    if (w == 0) {
        int y = ws[lane];
        #pragma unroll
        for (int d = 1; d < 32; d <<= 1) {
            int z = __shfl_up_sync(0xffffffffu, y, d);
            if (lane >= d) y += z;
        }
        ws[lane] = y;
    }
    __syncthreads();
    int incl = x + ((w > 0) ? ws[w - 1] : 0);
    if (n < NN) g_incl[n] = incl;
    if (threadIdx.x == 1023) g_bsum[blockIdx.x] = incl;
}

// ---------------- scan phase B: scan block sums (1 block) ----------------
__global__ void k_scanB() {
    __shared__ int s[64];
    int t = threadIdx.x;  // 64
    int v = (t < SCAN_BLOCKS) ? g_bsum[t] : 0;
    s[t] = v;
    __syncthreads();
    for (int d = 1; d < 64; d <<= 1) {
        int y = (t >= d) ? s[t - d] : 0;
        __syncthreads();
        s[t] += y;
        __syncthreads();
    }
    if (t < SCAN_BLOCKS) g_bpre[t] = s[t] - v;  // exclusive
}

// ---------------- scan phase C: fixup -> off + cursor ----------------
__global__ void k_scanC() {
    int n = blockIdx.x * 1024 + threadIdx.x;
    if (n < NN) {
        int off = g_incl[n] - g_deg[n] + g_bpre[blockIdx.x];
        g_off[n] = off;
        g_cursor[n] = off;
    }
}

// ---------------- scatter edge ids into dst-grouped order ----------------
__global__ void k_scatter(const int* __restrict__ dst) {
    int e = blockIdx.x * blockDim.x + threadIdx.x;
    if (e < EE) {
        int d = dst[e];
        int p = atomicAdd(&g_cursor[d], 1);
        g_eperm[p] = e;
    }
}

// ---------------- node GEMM: 4 nodes per warp ----------------
__global__ void k_node(const float* __restrict__ nfeat,
                       const float* __restrict__ b_ne,
                       const float* __restrict__ b_self,
                       float* __restrict__ out_self) {
    int warp = (blockIdx.x * blockDim.x + threadIdx.x) >> 5;
    int lane = threadIdx.x & 31;
    int n0 = warp * 4;
    if (n0 >= NN) return;

    float xv[4][4];
    #pragma unroll
    for (int nk = 0; nk < 4; nk++)
        #pragma unroll
        for (int ch = 0; ch < 4; ch++)
            xv[nk][ch] = nfeat[(size_t)(n0 + nk) * 128 + ch * 32 + lane];

    int j4 = lane * 4;
    float4 ah[4], as[4];
    #pragma unroll
    for (int nk = 0; nk < 4; nk++) { ah[nk] = make_float4(0,0,0,0); as[nk] = make_float4(0,0,0,0); }

    #pragma unroll
    for (int ch = 0; ch < 4; ch++) {
        #pragma unroll
        for (int c = 0; c < 32; c++) {
            int k = ch * 32 + c;
            float4 w1 = *(const float4*)&g_W1T[k * 128 + j4];
            float4 ws = *(const float4*)&g_WsT[k * 128 + j4];
            #pragma unroll
            for (int nk = 0; nk < 4; nk++) {
                float xk = __shfl_sync(0xffffffffu, xv[nk][ch], c);
                ah[nk].x = fmaf(w1.x, xk, ah[nk].x); ah[nk].y = fmaf(w1.y, xk, ah[nk].y);
                ah[nk].z = fmaf(w1.z, xk, ah[nk].z); ah[nk].w = fmaf(w1.w, xk, ah[nk].w);
                as[nk].x = fmaf(ws.x, xk, as[nk].x); as[nk].y = fmaf(ws.y, xk, as[nk].y);
                as[nk].z = fmaf(ws.z, xk, as[nk].z); as[nk].w = fmaf(ws.w, xk, as[nk].w);
            }
        }
    }
    float4 bh = *(const float4*)&b_ne[j4];
    float4 bs = *(const float4*)&b_self[j4];
    #pragma unroll
    for (int nk = 0; nk < 4; nk++) {
        float4 a = ah[nk], b = as[nk];
        a.x += bh.x; a.y += bh.y; a.z += bh.z; a.w += bh.w;
        b.x += bs.x; b.y += bs.y; b.z += bs.z; b.w += bs.w;
        *(float4*)&g_h1[(size_t)(n0 + nk) * 128 + j4] = a;
        *(float4*)&out_self[(size_t)(n0 + nk) * 128 + j4] = b;
    }
}

// ---------------- edge kernel: warp per dst, 8 edges per pass, fused epilogue ----------------
#define ETILE 8
__global__ void k_edge(const float* __restrict__ etype,
                       const int* __restrict__ src,
                       const float* __restrict__ eps,
                       float* __restrict__ out) {
    __shared__ float sW[EDGE_DIM * 128];
    for (int i = threadIdx.x; i < EDGE_DIM * 128; i += blockDim.x)
        sW[i] = g_WcT[i];
    __syncthreads();

    int lane = threadIdx.x & 31;
    int warp = (blockIdx.x * blockDim.x + threadIdx.x) >> 5;
    if (warp >= NN) return;
    int d = warp;
    int start = g_off[d];
    int cnt = g_deg[d];
    int j4 = lane * 4;

    float4 best = make_float4(0.f, 0.f, 0.f, 0.f);

    for (int i = 0; i < cnt; i += ETILE) {
        int m = cnt - i; if (m > ETILE) m = ETILE;
        float ev[ETILE];
        float4 acc[ETILE];
        int e0 = g_eperm[start + i];
        #pragma unroll
        for (int k = 0; k < ETILE; k++) {
            int e = (k < m) ? g_eperm[start + i + k] : e0;
            int s = src[e];
            ev[k] = etype[(size_t)e * 32 + lane];
            acc[k] = *(const float4*)&g_h1[(size_t)s * 128 + j4];
        }
        #pragma unroll
        for (int c = 0; c < 32; c++) {
            float4 w = *(const float4*)&sW[c * 128 + j4];
            #pragma unroll
            for (int k = 0; k < ETILE; k++) {
                float xc = __shfl_sync(0xffffffffu, ev[k], c);
                acc[k].x = fmaf(w.x, xc, acc[k].x);
                acc[k].y = fmaf(w.y, xc, acc[k].y);
                acc[k].z = fmaf(w.z, xc, acc[k].z);
                acc[k].w = fmaf(w.w, xc, acc[k].w);
            }
        }
        #pragma unroll
        for (int k = 0; k < ETILE; k++) {
            if (k < m) {
                best.x = fmaxf(best.x, acc[k].x);
                best.y = fmaxf(best.y, acc[k].y);
                best.z = fmaxf(best.z, acc[k].z);
                best.w = fmaxf(best.w, acc[k].w);
            }
        }
    }
    // fused epilogue: out currently holds self term (from k_node)
    float sc = 1.0f + eps[0];
    float4 o = *(const float4*)&out[(size_t)d * 128 + j4];
    o.x = fmaf(sc, best.x, o.x);
    o.y = fmaf(sc, best.y, o.y);
    o.z = fmaf(sc, best.z, o.z);
    o.w = fmaf(sc, best.w, o.w);
    *(float4*)&out[(size_t)d * 128 + j4] = o;
}

extern "C" void kernel_launch(void* const* d_in, const int* in_sizes, int n_in,
                              void* d_out, int out_size) {
    const float* nfeat  = (const float*)d_in[0];
    const float* etype  = (const float*)d_in[1];
    const int*   src    = (const int*)d_in[2];
    const int*   dst    = (const int*)d_in[3];
    const float* W_edge = (const float*)d_in[4];
    const float* W_ne   = (const float*)d_in[5];
    const float* b_ne   = (const float*)d_in[6];
    const float* W_self = (const float*)d_in[7];
    const float* b_self = (const float*)d_in[8];
    const float* eps    = (const float*)d_in[9];
    float* out = (float*)d_out;

    k_wc<<<32, 128>>>(W_ne, W_edge);
    k_prep<<<64, 256>>>(W_ne, W_self);
    k_count<<<(EE + 255) / 256, 256>>>(dst);
    k_scanA<<<SCAN_BLOCKS, 1024>>>();
    k_scanB<<<1, 64>>>();
    k_scanC<<<SCAN_BLOCKS, 1024>>>();
    k_scatter<<<(EE + 255) / 256, 256>>>(dst);
    k_node<<<(NN / 4 + 7) / 8, 256>>>(nfeat, b_ne, b_self, out);
    k_edge<<<(NN + 7) / 8, 256>>>(etype, src, eps, out);
}

// round 4
// speedup vs baseline: 2.1410x; 1.1036x over previous
#include <cuda_runtime.h>
#include <cstdint>

#define NN 50000
#define EE 800000
#define IN_DIM 128
#define EDGE_DIM 32
#define OUT_DIM 128
#define SCAN_BLOCKS 49
#define ETILE 8

typedef unsigned long long u64;

// Scratch (device globals; no dynamic allocation allowed)
__device__ float g_h1[(size_t)NN * OUT_DIM];     // W1 @ nfeat[n] + b_ne
__device__ float g_WcT[EDGE_DIM * OUT_DIM];      // (W2 @ W_edge)T: [c][o]
__device__ float g_W1T[IN_DIM * OUT_DIM];        // W1T: [k][j]
__device__ float g_WsT[IN_DIM * OUT_DIM];        // W_selfT: [k][j]
__device__ int   g_deg[NN];
__device__ int   g_incl[NN];
__device__ int   g_off[NN];
__device__ int   g_cursor[NN];
__device__ int   g_bsum[64];
__device__ int   g_bpre[64];
__device__ int   g_eperm[EE];                    // edge ids grouped by dst
__device__ int   g_esrc[EE];                     // src ids grouped by dst

// ---------------- packed fp32x2 helpers (exact fp32 semantics) ----------------
__device__ __forceinline__ u64 pk2(float a, float b) {
    u64 r; asm("mov.b64 %0, {%1, %2};" : "=l"(r) : "f"(a), "f"(b)); return r;
}
__device__ __forceinline__ void fma2(u64& d, u64 a, u64 b) {
    asm("fma.rn.f32x2 %0, %1, %2, %0;" : "+l"(d) : "l"(a), "l"(b));
}
__device__ __forceinline__ float2 up2(u64 v) {
    float2 f; asm("mov.b64 {%0, %1}, %2;" : "=f"(f.x), "=f"(f.y) : "l"(v)); return f;
}

// ---------------- prep: Wc = W2 @ W_edge, stored transposed ----------------
__global__ void k_wc(const float* __restrict__ W_ne, const float* __restrict__ W_edge) {
    int c = blockIdx.x;    // 0..31
    int o = threadIdx.x;   // 0..127
    float s = 0.f;
    #pragma unroll 8
    for (int j = 0; j < 128; j++)
        s += W_ne[o * 256 + 128 + j] * W_edge[j * 32 + c];
    g_WcT[c * 128 + o] = s;
}

// ---------------- prep: transpose W1 and W_self; zero deg ----------------
__global__ void k_prep(const float* __restrict__ W_ne, const float* __restrict__ W_self) {
    int idx = blockIdx.x * blockDim.x + threadIdx.x;  // 16384
    int j = idx >> 7, k = idx & 127;
    g_W1T[k * 128 + j] = W_ne[j * 256 + k];
    g_WsT[k * 128 + j] = W_self[j * 128 + k];
    for (int n = idx; n < NN; n += 16384) g_deg[n] = 0;
}

// ---------------- degree count ----------------
__global__ void k_count(const int* __restrict__ dst) {
    int e = blockIdx.x * blockDim.x + threadIdx.x;
    if (e < EE) atomicAdd(&g_deg[dst[e]], 1);
}

// ---------------- scan A: per-block inclusive scan ----------------
__global__ void k_scanA() {
    int n = blockIdx.x * 1024 + threadIdx.x;
    int lane = threadIdx.x & 31, w = threadIdx.x >> 5;
    int v = (n < NN) ? g_deg[n] : 0;
    int x = v;
    #pragma unroll
    for (int d = 1; d < 32; d <<= 1) {
        int y = __shfl_up_sync(0xffffffffu, x, d);
        if (lane >= d) x += y;
    }
    __shared__ int ws[32];
    if (lane == 31) ws[w] = x;
    __syncthreads();
    if (w == 0) {
        int y = ws[lane];
        #pragma unroll
        for (int d = 1; d < 32; d <<= 1) {
            int z = __shfl_up_sync(0xffffffffu, y, d);
            if (lane >= d) y += z;
        }
        ws[lane] = y;
    }
    __syncthreads();
    int incl = x + ((w > 0) ? ws[w - 1] : 0);
    if (n < NN) g_incl[n] = incl;
    if (threadIdx.x == 1023) g_bsum[blockIdx.x] = incl;
}

// ---------------- scan B: block sums ----------------
__global__ void k_scanB() {
    __shared__ int s[64];
    int t = threadIdx.x;
    int v = (t < SCAN_BLOCKS) ? g_bsum[t] : 0;
    s[t] = v;
    __syncthreads();
    for (int d = 1; d < 64; d <<= 1) {
        int y = (t >= d) ? s[t - d] : 0;
        __syncthreads();
        s[t] += y;
        __syncthreads();
    }
    if (t < SCAN_BLOCKS) g_bpre[t] = s[t] - v;
}

// ---------------- scan C: fixup ----------------
__global__ void k_scanC() {
    int n = blockIdx.x * 1024 + threadIdx.x;
    if (n < NN) {
        int off = g_incl[n] - g_deg[n] + g_bpre[blockIdx.x];
        g_off[n] = off;
        g_cursor[n] = off;
    }
}

// ---------------- scatter: edge id + src (src read coalesced here) ----------------
__global__ void k_scatter(const int* __restrict__ dst, const int* __restrict__ src) {
    int e = blockIdx.x * blockDim.x + threadIdx.x;
    if (e < EE) {
        int d = dst[e];
        int s = src[e];
        int p = atomicAdd(&g_cursor[d], 1);
        g_eperm[p] = e;
        g_esrc[p] = s;
    }
}

// ---------------- node GEMM: 4 nodes/warp, f32x2 packed ----------------
__global__ void __launch_bounds__(256) k_node(const float* __restrict__ nfeat,
                       const float* __restrict__ b_ne,
                       const float* __restrict__ b_self,
                       float* __restrict__ out_self) {
    int warp = (blockIdx.x * blockDim.x + threadIdx.x) >> 5;
    int lane = threadIdx.x & 31;
    int n0 = warp * 4;
    if (n0 >= NN) return;

    float xv[4][4];
    #pragma unroll
    for (int nk = 0; nk < 4; nk++)
        #pragma unroll
        for (int ch = 0; ch < 4; ch++)
            xv[nk][ch] = nfeat[(size_t)(n0 + nk) * 128 + ch * 32 + lane];

    int j4 = lane * 4;
    // acc pairs over adjacent output dims: ah[nk][0]={j4,j4+1}, ah[nk][1]={j4+2,j4+3}
    u64 ah[4][2], as[4][2];
    #pragma unroll
    for (int nk = 0; nk < 4; nk++) {
        ah[nk][0] = 0ull; ah[nk][1] = 0ull;
        as[nk][0] = 0ull; as[nk][1] = 0ull;
    }

    const u64* W1p = (const u64*)g_W1T;
    const u64* Wsp = (const u64*)g_WsT;

    #pragma unroll
    for (int ch = 0; ch < 4; ch++) {
        #pragma unroll
        for (int c = 0; c < 32; c++) {
            int k = ch * 32 + c;
            u64 w1a = W1p[k * 64 + lane * 2];
            u64 w1b = W1p[k * 64 + lane * 2 + 1];
            u64 wsa = Wsp[k * 64 + lane * 2];
            u64 wsb = Wsp[k * 64 + lane * 2 + 1];
            #pragma unroll
            for (int nk = 0; nk < 4; nk++) {
                float xk = __shfl_sync(0xffffffffu, xv[nk][ch], c);
                u64 x2 = pk2(xk, xk);
                fma2(ah[nk][0], w1a, x2);
                fma2(ah[nk][1], w1b, x2);
                fma2(as[nk][0], wsa, x2);
                fma2(as[nk][1], wsb, x2);
            }
        }
    }
    float4 bh = *(const float4*)&b_ne[j4];
    float4 bs = *(const float4*)&b_self[j4];
    #pragma unroll
    for (int nk = 0; nk < 4; nk++) {
        float2 a0 = up2(ah[nk][0]), a1 = up2(ah[nk][1]);
        float2 s0 = up2(as[nk][0]), s1 = up2(as[nk][1]);
        float4 a = make_float4(a0.x + bh.x, a0.y + bh.y, a1.x + bh.z, a1.y + bh.w);
        float4 b = make_float4(s0.x + bs.x, s0.y + bs.y, s1.x + bs.z, s1.y + bs.w);
        *(float4*)&g_h1[(size_t)(n0 + nk) * 128 + j4] = a;
        *(float4*)&out_self[(size_t)(n0 + nk) * 128 + j4] = b;
    }
}

// ---------------- edge kernel: warp per dst, 8 edges/tile, f32x2, no shuffle in hot loop ----------------
// Pairing: acc[p][jj] = { m_{2p}[j4+jj], m_{2p+1}[j4+jj] }
// multiplier pair {e_{2p}[c], e_{2p+1}[c]} comes from transposed shared stage as one LDS.64 broadcast
__global__ void __launch_bounds__(256) k_edge(const float* __restrict__ etype,
                       const float* __restrict__ eps,
                       float* __restrict__ out) {
    __shared__ __align__(16) float sW[EDGE_DIM * 128];      // 16 KB: [c][j]
    __shared__ __align__(16) float sE[8][EDGE_DIM * 10];    // per-warp stage, stride 10 keeps pairs 8B-aligned
    for (int i = threadIdx.x; i < EDGE_DIM * 128; i += 256)
        sW[i] = g_WcT[i];
    __syncthreads();

    int lane = threadIdx.x & 31;
    int wip = threadIdx.x >> 5;
    int d = blockIdx.x * 8 + wip;      // grid sized exactly: 6250*8 = 50000
    int start = g_off[d];
    int cnt = g_deg[d];
    int j4 = lane * 4;
    float* sEw = &sE[wip][0];
    int kq = lane >> 2;            // edge slot this lane stages (0..7)
    int cb = (lane & 3) * 8;       // column base (0,8,16,24)

    float best0 = 0.f, best1 = 0.f, best2 = 0.f, best3 = 0.f;

    for (int i = 0; i < cnt; i += ETILE) {
        int m = cnt - i; if (m > ETILE) m = ETILE;
        int e_l = 0, s_l = 0;
        if (lane < ETILE) {
            int idx = start + i + ((lane < m) ? lane : 0);  // pad with edge0 (harmless for max)
            e_l = g_eperm[idx];
            s_l = g_esrc[idx];
        }
        // stage etype tile transposed: sE[c*10 + k] = etype[e_k*32 + c]
        int ek = __shfl_sync(0xffffffffu, e_l, kq);
        float4 a = *(const float4*)&etype[(size_t)ek * 32 + cb];
        float4 b = *(const float4*)&etype[(size_t)ek * 32 + cb + 4];
        sEw[(cb + 0) * 10 + kq] = a.x; sEw[(cb + 1) * 10 + kq] = a.y;
        sEw[(cb + 2) * 10 + kq] = a.z; sEw[(cb + 3) * 10 + kq] = a.w;
        sEw[(cb + 4) * 10 + kq] = b.x; sEw[(cb + 5) * 10 + kq] = b.y;
        sEw[(cb + 6) * 10 + kq] = b.z; sEw[(cb + 7) * 10 + kq] = b.w;

        // init acc with gathered h1 pairs
        u64 acc[4][4];
        #pragma unroll
        for (int p = 0; p < 4; p++) {
            int s0 = __shfl_sync(0xffffffffu, s_l, 2 * p);
            int s1 = __shfl_sync(0xffffffffu, s_l, 2 * p + 1);
            float4 h0 = *(const float4*)&g_h1[(size_t)s0 * 128 + j4];
            float4 h1v = *(const float4*)&g_h1[(size_t)s1 * 128 + j4];
            acc[p][0] = pk2(h0.x, h1v.x); acc[p][1] = pk2(h0.y, h1v.y);
            acc[p][2] = pk2(h0.z, h1v.z); acc[p][3] = pk2(h0.w, h1v.w);
        }
        __syncwarp();

        #pragma unroll
        for (int c = 0; c < 32; c++) {
            float4 w = *(const float4*)&sW[c * 128 + j4];
            u64 w0 = pk2(w.x, w.x), w1 = pk2(w.y, w.y);
            u64 w2 = pk2(w.z, w.z), w3 = pk2(w.w, w.w);
            const u64* ep = (const u64*)(sEw + c * 10);
            #pragma unroll
            for (int p = 0; p < 4; p++) {
                u64 ce = ep[p];   // broadcast LDS.64: {e_{2p}[c], e_{2p+1}[c]}
                fma2(acc[p][0], w0, ce);
                fma2(acc[p][1], w1, ce);
                fma2(acc[p][2], w2, ce);
                fma2(acc[p][3], w3, ce);
            }
        }
        __syncwarp();

        #pragma unroll
        for (int p = 0; p < 4; p++) {
            float2 f0 = up2(acc[p][0]); float2 f1 = up2(acc[p][1]);
            float2 f2 = up2(acc[p][2]); float2 f3 = up2(acc[p][3]);
            best0 = fmaxf(best0, fmaxf(f0.x, f0.y));
            best1 = fmaxf(best1, fmaxf(f1.x, f1.y));
            best2 = fmaxf(best2, fmaxf(f2.x, f2.y));
            best3 = fmaxf(best3, fmaxf(f3.x, f3.y));
        }
    }
    // relu absorbed: best starts at 0, max(0, max_k x_k) == max_k relu(x_k)
    // fused epilogue: out holds self term from k_node
    float sc = 1.0f + eps[0];
    float4 o = *(const float4*)&out[(size_t)d * 128 + j4];
    o.x = fmaf(sc, best0, o.x);
    o.y = fmaf(sc, best1, o.y);
    o.z = fmaf(sc, best2, o.z);
    o.w = fmaf(sc, best3, o.w);
    *(float4*)&out[(size_t)d * 128 + j4] = o;
}

extern "C" void kernel_launch(void* const* d_in, const int* in_sizes, int n_in,
                              void* d_out, int out_size) {
    const float* nfeat  = (const float*)d_in[0];
    const float* etype  = (const float*)d_in[1];
    const int*   src    = (const int*)d_in[2];
    const int*   dst    = (const int*)d_in[3];
    const float* W_edge = (const float*)d_in[4];
    const float* W_ne   = (const float*)d_in[5];
    const float* b_ne   = (const float*)d_in[6];
    const float* W_self = (const float*)d_in[7];
    const float* b_self = (const float*)d_in[8];
    const float* eps    = (const float*)d_in[9];
    float* out = (float*)d_out;

    k_wc<<<32, 128>>>(W_ne, W_edge);
    k_prep<<<64, 256>>>(W_ne, W_self);
    k_count<<<(EE + 255) / 256, 256>>>(dst);
    k_scanA<<<SCAN_BLOCKS, 1024>>>();
    k_scanB<<<1, 64>>>();
    k_scanC<<<SCAN_BLOCKS, 1024>>>();
    k_scatter<<<(EE + 255) / 256, 256>>>(dst, src);
    k_node<<<(NN / 4 + 7) / 8, 256>>>(nfeat, b_ne, b_self, out);
    k_edge<<<NN / 8, 256>>>(etype, eps, out);
}